// round 3
// baseline (speedup 1.0000x reference)
#include <cuda_runtime.h>
#include <cuda_bf16.h>

// NeRF deterministic inverse-CDF sampling.
// R rays, 127 weights/ray -> 128-bin CDF -> 128 output samples/ray.
// One warp per ray:
//   - near/far cube intersection (bound=1), IEEE division for robustness
//   - coalesced weight load (4 floats/lane), warp inclusive scan -> CDF in smem
//   - per-lane binary search (7 iters) with value tracking, fused interp.
// Bins are affine in index: z[i] = near + s*i, s=(far-near)/127, so output
// = near + s*(below + t) with above-below == 1 always (cdf[0]=0 <= u < cdf[127]).

#define RAYS_PER_BLOCK 8
#define FULL 0xffffffffu

__device__ __forceinline__ float warp_incl_scan(float x, int lane) {
#pragma unroll
    for (int d = 1; d < 32; d <<= 1) {
        float y = __shfl_up_sync(FULL, x, d);
        if (lane >= d) x += y;
    }
    return x;
}

__global__ __launch_bounds__(RAYS_PER_BLOCK * 32)
void nerf_sample_kernel(const float* __restrict__ rays_o,
                        const float* __restrict__ rays_d,
                        const float* __restrict__ weights,
                        float* __restrict__ out,
                        int R)
{
    __shared__ float s_cdf[RAYS_PER_BLOCK][128];

    const int warp = threadIdx.x >> 5;
    const int lane = threadIdx.x & 31;
    const int ray  = blockIdx.x * RAYS_PER_BLOCK + warp;
    if (ray >= R) return;

    // ---- near/far cube intersection (all lanes redundant; L1 broadcast) ----
    const float bound = 1.0f;
    const float* o3 = rays_o + 3 * ray;
    const float* d3 = rays_d + 3 * ray;
    float nearv = -1e30f, farv = 1e30f;
#pragma unroll
    for (int a = 0; a < 3; ++a) {
        float oo = __ldg(o3 + a);
        float dd = __ldg(d3 + a) + 1e-15f;
        float t0 = (-bound - oo) / dd;   // IEEE div: intermediates can be huge
        float t1 = ( bound - oo) / dd;
        nearv = fmaxf(nearv, fminf(t0, t1));
        farv  = fminf(farv,  fmaxf(t0, t1));
    }
    nearv = fmaxf(nearv, 0.05f);
    const float sstep = (farv - nearv) * (1.0f / 127.0f);

    // ---- load 127 weights (coalesced), +eps, 4-segment warp inclusive scan ----
    const float* wrow = weights + (long long)ray * 127;
    float w0 = __ldg(wrow + lane)      + 1e-5f;
    float w1 = __ldg(wrow + lane + 32) + 1e-5f;
    float w2 = __ldg(wrow + lane + 64) + 1e-5f;
    float w3 = (lane < 31) ? (__ldg(wrow + lane + 96) + 1e-5f) : 0.0f;

    float p0 = warp_incl_scan(w0, lane);
    float t0 = __shfl_sync(FULL, p0, 31);
    float p1 = warp_incl_scan(w1, lane) + t0;
    float t1 = __shfl_sync(FULL, p1, 31);
    float p2 = warp_incl_scan(w2, lane) + t1;
    float t2 = __shfl_sync(FULL, p2, 31);
    float p3 = warp_incl_scan(w3, lane) + t2;
    float total = __shfl_sync(FULL, p3, 31);
    const float rtot = __fdividef(1.0f, total);

    // ---- stage normalized CDF (length 128, leading 0) in shared ----
    float* cdf = s_cdf[warp];
    if (lane == 0) cdf[0] = 0.0f;
    cdf[1 + lane]  = p0 * rtot;
    cdf[33 + lane] = p1 * rtot;
    cdf[65 + lane] = p2 * rtot;
    if (lane < 31) cdf[97 + lane] = p3 * rtot;
    __syncwarp();

    // ---- 4 outputs per lane: binary search + fused interp ----
    float* orow = out + (long long)ray * 128;
    const float vtop = cdf[127];
#pragma unroll
    for (int q = 0; q < 4; ++q) {
        const int j = q * 32 + lane;
        const float u = fmaf((float)j, 0.0078125f, 0.00390625f);  // (j+0.5)/128

        int lo = 0, hi = 127;
        float vlo = 0.0f, vhi = vtop;
#pragma unroll
        for (int it = 0; it < 7; ++it) {
            int mid = (lo + hi) >> 1;
            float vm = cdf[mid];
            bool go = (vm <= u);          // searchsorted side='right'
            lo  = go ? mid : lo;
            vlo = go ? vm  : vlo;
            hi  = go ? hi  : mid;
            vhi = go ? vhi : vm;
        }
        float denom = vhi - vlo;
        denom = (denom < 1e-5f) ? 1.0f : denom;
        float t = __fdividef(u - vlo, denom);
        orow[j] = fmaf(sstep, (float)lo + t, nearv);
    }
}

extern "C" void kernel_launch(void* const* d_in, const int* in_sizes, int n_in,
                              void* d_out, int out_size) {
    const float* rays_o  = (const float*)d_in[0];
    const float* rays_d  = (const float*)d_in[1];
    const float* weights = (const float*)d_in[2];
    float* out = (float*)d_out;

    const int R = in_sizes[0] / 3;   // 262144
    dim3 block(RAYS_PER_BLOCK * 32);
    dim3 grid((R + RAYS_PER_BLOCK - 1) / RAYS_PER_BLOCK);
    nerf_sample_kernel<<<grid, block>>>(rays_o, rays_d, weights, out, R);
}

// round 4
// speedup vs baseline: 1.0483x; 1.0483x over previous
#include <cuda_runtime.h>
#include <cuda_bf16.h>

// NeRF deterministic inverse-CDF sampling — SCATTER formulation.
// One warp per ray. Instead of per-sample binary search over the CDF (gather),
// each lane owns bins and computes directly which uniform samples
// u_j = (j+0.5)/128 land in its bin:  j in [ceil(128*cdf_lo-0.5), ceil(128*cdf_hi-0.5)).
// Adjacent bins derive their shared boundary from the SAME register value with the
// SAME fp ops, so the ranges partition [0,128) exactly: every output written once.
// No shared memory, no binary search.

#define RAYS_PER_BLOCK 8
#define FULL 0xffffffffu

__device__ __forceinline__ float warp_incl_scan(float x, int lane) {
#pragma unroll
    for (int d = 1; d < 32; d <<= 1) {
        float y = __shfl_up_sync(FULL, x, d);
        if (lane >= d) x += y;
    }
    return x;
}

__global__ __launch_bounds__(RAYS_PER_BLOCK * 32)
void nerf_sample_kernel(const float* __restrict__ rays_o,
                        const float* __restrict__ rays_d,
                        const float* __restrict__ weights,
                        float* __restrict__ out,
                        int R)
{
    const int warp = threadIdx.x >> 5;
    const int lane = threadIdx.x & 31;
    const int ray  = blockIdx.x * RAYS_PER_BLOCK + warp;
    if (ray >= R) return;

    // ---- near/far cube intersection (bound=1); all lanes redundant ----
    const float bound = 1.0f;
    const float* o3 = rays_o + 3 * ray;
    const float* d3 = rays_d + 3 * ray;
    float nearv = -1e30f, farv = 1e30f;
#pragma unroll
    for (int a = 0; a < 3; ++a) {
        float oo = __ldg(o3 + a);
        float dd = __ldg(d3 + a) + 1e-15f;
        float t0 = (-bound - oo) / dd;   // IEEE div: intermediates can be huge
        float t1 = ( bound - oo) / dd;
        nearv = fmaxf(nearv, fminf(t0, t1));
        farv  = fminf(farv,  fmaxf(t0, t1));
    }
    nearv = fmaxf(nearv, 0.05f);
    const float sstep = (farv - nearv) * (1.0f / 127.0f);

    // ---- load 127 weights (coalesced), +eps, 4-segment warp inclusive scan ----
    const float* wrow = weights + (long long)ray * 127;
    float w0 = __ldg(wrow + lane)      + 1e-5f;
    float w1 = __ldg(wrow + lane + 32) + 1e-5f;
    float w2 = __ldg(wrow + lane + 64) + 1e-5f;
    float w3 = (lane < 31) ? (__ldg(wrow + lane + 96) + 1e-5f) : 0.0f;

    float p0 = warp_incl_scan(w0, lane);
    float c1 = __shfl_sync(FULL, p0, 31);
    float p1 = warp_incl_scan(w1, lane) + c1;
    float c2 = __shfl_sync(FULL, p1, 31);
    float p2 = warp_incl_scan(w2, lane) + c2;
    float c3 = __shfl_sync(FULL, p2, 31);
    float p3 = warp_incl_scan(w3, lane) + c3;
    float total = __shfl_sync(FULL, p3, 31);   // lane31 w3=0 -> p3[31] = sum of 127
    const float rtot = __fdividef(1.0f, total);

    // ---- scatter: each lane emits the samples falling in its 4 bins ----
    float* orow = out + (long long)ray * 128;

    const float pv[4] = {p0, p1, p2, p3};
    const float cv[4] = {0.0f, c1, c2, c3};

#pragma unroll
    for (int q = 0; q < 4; ++q) {
        float p     = pv[q];
        float pprev = __shfl_up_sync(FULL, p, 1);
        if (lane == 0) pprev = cv[q];

        const int i = q * 32 + lane;          // bin index, valid for i < 127
        float cdf_lo = pprev * rtot;
        float cdf_hi = p * rtot;

        int jlo = (int)ceilf(fmaf(cdf_lo, 128.0f, -0.5f));
        int jhi = (int)ceilf(fmaf(cdf_hi, 128.0f, -0.5f));
        jlo = max(jlo, 0);
        jhi = min(jhi, 128);

        if (i < 127 && jlo < jhi) {
            float denom = cdf_hi - cdf_lo;
            float rden  = (denom < 1e-5f) ? 1.0f : __fdividef(1.0f, denom);
            float fi = (float)i;
            float uj = fmaf((float)jlo, 0.0078125f, 0.00390625f);  // (jlo+0.5)/128
            for (int j = jlo; j < jhi; ++j) {
                float t = (uj - cdf_lo) * rden;
                orow[j] = fmaf(sstep, fi + t, nearv);
                uj += 0.0078125f;
            }
        }
    }
}

extern "C" void kernel_launch(void* const* d_in, const int* in_sizes, int n_in,
                              void* d_out, int out_size) {
    const float* rays_o  = (const float*)d_in[0];
    const float* rays_d  = (const float*)d_in[1];
    const float* weights = (const float*)d_in[2];
    float* out = (float*)d_out;

    const int R = in_sizes[0] / 3;   // 262144
    dim3 block(RAYS_PER_BLOCK * 32);
    dim3 grid((R + RAYS_PER_BLOCK - 1) / RAYS_PER_BLOCK);
    nerf_sample_kernel<<<grid, block>>>(rays_o, rays_d, weights, out, R);
}

// round 5
// speedup vs baseline: 1.2151x; 1.1590x over previous
#include <cuda_runtime.h>
#include <cuda_bf16.h>

// NeRF deterministic inverse-CDF sampling — lane-minor scatter + smem staging.
// One warp per ray (R=262144, 127 weights -> 128-bin CDF -> 128 samples).
// Lane l owns bins 4l..4l+3:
//   3 serial adds + single 32-wide warp scan (replaces 4 segment scans).
//   Lane sample-range boundaries derived from identical fmaf on identical
//   values (own incl vs shfl_up incl) -> exact warp-wide partition of [0,128).
//   Interior bin boundaries are lane-private, monotone-clamped.
// Output is affine in sample index within a bin: out_j = A*j + B, so the
// divergent inner loop is 5 instrs/iter into a smem staging row; final
// writeback is one LDS.128 + STG.128 per lane (fully coalesced).

#define RPB 8
#define FULL 0xffffffffu

__global__ __launch_bounds__(RPB * 32)
void nerf_sample_kernel(const float* __restrict__ rays_o,
                        const float* __restrict__ rays_d,
                        const float* __restrict__ weights,
                        float* __restrict__ out,
                        int R)
{
    __shared__ __align__(16) float s_out[RPB][128];

    const int warp = threadIdx.x >> 5;
    const int lane = threadIdx.x & 31;
    const int ray  = blockIdx.x * RPB + warp;
    if (ray >= R) return;

    // ---- near/far cube intersection (bound=1); warp-redundant ----
    const float* o3 = rays_o + 3 * ray;
    const float* d3 = rays_d + 3 * ray;
    float nearv = -1e30f, farv = 1e30f;
#pragma unroll
    for (int a = 0; a < 3; ++a) {
        float oo  = __ldg(o3 + a);
        float dd  = __ldg(d3 + a) + 1e-15f;
        float inv = __fdividef(1.0f, dd);
        float t0  = (-1.0f - oo) * inv;
        float t1  = ( 1.0f - oo) * inv;
        nearv = fmaxf(nearv, fminf(t0, t1));
        farv  = fminf(farv,  fmaxf(t0, t1));
    }
    nearv = fmaxf(nearv, 0.05f);
    const float sstep = (farv - nearv) * (1.0f / 127.0f);

    // ---- lane-minor weight load: lane l owns w[4l..4l+3] ----
    const float* wrow = weights + (long long)ray * 127;
    const int base = 4 * lane;
    float w0 = __ldg(wrow + base)     + 1e-5f;
    float w1 = __ldg(wrow + base + 1) + 1e-5f;
    float w2 = __ldg(wrow + base + 2) + 1e-5f;
    float w3 = (lane < 31) ? (__ldg(wrow + base + 3) + 1e-5f) : 0.0f;

    // local inclusive prefix + one warp scan over lane totals
    const float s0 = w0;
    const float s1 = s0 + w1;
    const float s2 = s1 + w2;
    const float s3 = s2 + w3;

    float incl = s3;
#pragma unroll
    for (int d = 1; d < 32; d <<= 1) {
        float y = __shfl_up_sync(FULL, incl, d);
        if (lane >= d) incl += y;
    }
    float P = __shfl_up_sync(FULL, incl, 1);
    if (lane == 0) P = 0.0f;
    const float total = __shfl_sync(FULL, incl, 31);
    const float rtot  = __fdividef(1.0f, total);
    const float g     = rtot * 128.0f;   // identical in all lanes

    // normalized CDF boundaries for this lane's 4 bins
    const float m1 = P + s0, m2 = P + s1, m3 = P + s2;
    const float b0 = P   * rtot;
    const float b1 = m1  * rtot;
    const float b2 = m2  * rtot;
    const float b3 = m3  * rtot;
    const float b4 = incl * rtot;

    // sample-index boundaries; jb4(lane l) == jb0(lane l+1) exactly
    int jb0 = (int)ceilf(fmaf(P,    g, -0.5f));
    int jb4 = (int)ceilf(fmaf(incl, g, -0.5f));
    jb0 = min(max(jb0, 0), 128);
    jb4 = min(max(jb4, 0), 128);
    int jb1 = min(max((int)ceilf(fmaf(m1, g, -0.5f)), jb0), jb4);
    int jb2 = min(max((int)ceilf(fmaf(m2, g, -0.5f)), jb1), jb4);
    int jb3 = min(max((int)ceilf(fmaf(m3, g, -0.5f)), jb2), jb4);

    float* srow = s_out[warp];
    const float sA = sstep * 0.0078125f;   // sstep/128
    const float fi = (float)base;

    // per-bin affine emission: out_j = A*j + B
#define EMIT(JL, JH, BLO, BHI, FI) do {                                   \
        const int jl = (JL), jh = (JH);                                   \
        if (jl < jh) {                                                    \
            float den  = (BHI) - (BLO);                                   \
            float rden = (den < 1e-5f) ? 1.0f : __fdividef(1.0f, den);    \
            float A = sA * rden;                                          \
            float B = fmaf(sstep, (FI) + (0.00390625f - (BLO)) * rden,    \
                           nearv);                                        \
            float v = fmaf(A, (float)jl, B);                              \
            for (int j = jl; j < jh; ++j) { srow[j] = v; v += A; }        \
        }                                                                 \
    } while (0)

    EMIT(jb0, jb1, b0, b1, fi);
    EMIT(jb1, jb2, b1, b2, fi + 1.0f);
    EMIT(jb2, jb3, b2, b3, fi + 2.0f);
    EMIT(jb3, jb4, b3, b4, fi + 3.0f);
#undef EMIT

    __syncwarp();

    // coalesced vectorized writeback
    float4 v4 = *reinterpret_cast<const float4*>(srow + base);
    *reinterpret_cast<float4*>(out + (long long)ray * 128 + base) = v4;
}

extern "C" void kernel_launch(void* const* d_in, const int* in_sizes, int n_in,
                              void* d_out, int out_size) {
    const float* rays_o  = (const float*)d_in[0];
    const float* rays_d  = (const float*)d_in[1];
    const float* weights = (const float*)d_in[2];
    float* out = (float*)d_out;

    const int R = in_sizes[0] / 3;   // 262144
    dim3 block(RPB * 32);
    dim3 grid((R + RPB - 1) / RPB);
    nerf_sample_kernel<<<grid, block>>>(rays_o, rays_d, weights, out, R);
}